// round 3
// baseline (speedup 1.0000x reference)
#include <cuda_runtime.h>
#include <math.h>

#define Bb 4
#define Ss 2048
#define Dd 1024
#define Hh 16
#define HDIM 64
#define BHn (Bb*Hh)      // 64
#define BSn (Bb*Ss)      // 8192
#define QKSCALE 0.3535533905932738f  // 64^-0.25

// ---------------- scratch (static device globals; no allocation) ----------------
// g_q doubles as g_attn: by the time softmax_pv writes the attn output, Q is dead
// (qk scores are already materialized in d_out).
__device__ float g_q[(size_t)BHn*Ss*HDIM];      // 33.5 MB, [b,h,s,hd] roped+scaled; later [b,s,d] pre-Wo
__device__ float g_k[(size_t)BHn*Ss*HDIM];      // 33.5 MB
__device__ float g_v[(size_t)BHn*Ss*HDIM];      // 33.5 MB
__device__ float g_cos[Ss*32];
__device__ float g_sin[Ss*32];

// ---------------- RoPE table ----------------
__global__ void rope_table_kernel(const float* __restrict__ inv_freq,
                                  const float* __restrict__ rbias) {
    int idx = blockIdx.x * blockDim.x + threadIdx.x;
    if (idx >= Ss * 32) return;
    int t = idx >> 5, j = idx & 31;
    float ang = (float)t * inv_freq[j] + rbias[t * 32 + j];
    float s, c;
    sincosf(ang, &s, &c);
    g_cos[idx] = c;
    g_sin[idx] = s;
}

// ---------------- fused QKV projection: y = x @ W^T (+bias), RoPE, scale ----------------
// grid: (N/128=8, M/128=64, 3), block 256. z: 0=Q, 1=K, 2=V
__global__ __launch_bounds__(256) void qkv_kernel(
    const float* __restrict__ x,
    const float* __restrict__ Wq, const float* __restrict__ bq,
    const float* __restrict__ Wk,
    const float* __restrict__ Wv, const float* __restrict__ bv)
{
    __shared__ float As[16][128];
    __shared__ float Bs[16][128];
    const int z = blockIdx.z;
    const float* W    = (z == 0) ? Wq : (z == 1) ? Wk : Wv;
    const float* bias = (z == 0) ? bq : (z == 2) ? bv : nullptr;
    const int m0 = blockIdx.y * 128, n0 = blockIdx.x * 128;
    const int t = threadIdx.x;
    const int lr = t >> 2, lc = (t & 3) << 2;
    const int ty = t >> 4, tx = t & 15;

    float acc[8][8];
#pragma unroll
    for (int i = 0; i < 8; i++)
#pragma unroll
        for (int j = 0; j < 8; j++) acc[i][j] = 0.f;

    for (int kk = 0; kk < 1024; kk += 16) {
#pragma unroll
        for (int hf = 0; hf < 2; hf++) {
            int r = lr + hf * 64;
            float4 va = *(const float4*)(x + (size_t)(m0 + r) * 1024 + kk + lc);
            As[lc + 0][r] = va.x; As[lc + 1][r] = va.y;
            As[lc + 2][r] = va.z; As[lc + 3][r] = va.w;
            float4 vb = *(const float4*)(W + (size_t)(n0 + r) * 1024 + kk + lc);
            Bs[lc + 0][r] = vb.x; Bs[lc + 1][r] = vb.y;
            Bs[lc + 2][r] = vb.z; Bs[lc + 3][r] = vb.w;
        }
        __syncthreads();
#pragma unroll
        for (int k = 0; k < 16; k++) {
            float a[8], b[8];
            *(float4*)(a)     = *(const float4*)&As[k][ty * 4];
            *(float4*)(a + 4) = *(const float4*)&As[k][ty * 4 + 64];
            *(float4*)(b)     = *(const float4*)&Bs[k][tx * 4];
            *(float4*)(b + 4) = *(const float4*)&Bs[k][tx * 4 + 64];
#pragma unroll
            for (int i = 0; i < 8; i++)
#pragma unroll
                for (int j = 0; j < 8; j++) acc[i][j] = fmaf(a[i], b[j], acc[i][j]);
        }
        __syncthreads();
    }

    // epilogue: bias, RoPE (adjacent col pairs are in-thread), scale, scatter to [b,h,s,hd]
#pragma unroll
    for (int i = 0; i < 8; i++) {
        int m = m0 + ty * 4 + (i & 3) + ((i >> 2) << 6);
        int s = m & (Ss - 1);
        int bidx = m >> 11;
#pragma unroll
        for (int j = 0; j < 8; j += 2) {
            int n = n0 + tx * 4 + (j & 3) + ((j >> 2) << 6);
            float yr = acc[i][j];
            float yi = acc[i][j + 1];
            if (bias != nullptr) { yr += bias[n]; yi += bias[n + 1]; }
            int h = n >> 6, hd = n & 63;
            size_t o = (((size_t)(bidx * Hh + h) * Ss + s) << 6) + hd;
            if (z == 2) {
                g_v[o] = yr; g_v[o + 1] = yi;
            } else {
                int jr = hd >> 1;
                float cs = g_cos[s * 32 + jr], sn = g_sin[s * 32 + jr];
                float rr = (yr * cs - yi * sn) * QKSCALE;
                float ii = (yr * sn + yi * cs) * QKSCALE;
                float* dst = (z == 0) ? g_q : g_k;
                dst[o] = rr; dst[o + 1] = ii;
            }
        }
    }
}

// ---------------- per-head scores: qk = Q K^T + mask, written to d_out qk region ----------------
// grid: (16, 16, 64), block 256
__global__ __launch_bounds__(256) void qk_kernel(const float* __restrict__ mask,
                                                 float* __restrict__ qk_out)
{
    __shared__ float As[16][128];
    __shared__ float Bs[16][128];
    const int bh = blockIdx.z;
    const float* A  = g_q + (size_t)bh * Ss * 64;
    const float* Bm = g_k + (size_t)bh * Ss * 64;
    const int m0 = blockIdx.y * 128, n0 = blockIdx.x * 128;
    const int t = threadIdx.x;
    const int lr = t >> 2, lc = (t & 3) << 2;
    const int ty = t >> 4, tx = t & 15;

    float acc[8][8];
#pragma unroll
    for (int i = 0; i < 8; i++)
#pragma unroll
        for (int j = 0; j < 8; j++) acc[i][j] = 0.f;

#pragma unroll
    for (int kk = 0; kk < 64; kk += 16) {
#pragma unroll
        for (int hf = 0; hf < 2; hf++) {
            int r = lr + hf * 64;
            float4 va = *(const float4*)(A + (size_t)(m0 + r) * 64 + kk + lc);
            As[lc + 0][r] = va.x; As[lc + 1][r] = va.y;
            As[lc + 2][r] = va.z; As[lc + 3][r] = va.w;
            float4 vb = *(const float4*)(Bm + (size_t)(n0 + r) * 64 + kk + lc);
            Bs[lc + 0][r] = vb.x; Bs[lc + 1][r] = vb.y;
            Bs[lc + 2][r] = vb.z; Bs[lc + 3][r] = vb.w;
        }
        __syncthreads();
#pragma unroll
        for (int k = 0; k < 16; k++) {
            float a[8], b[8];
            *(float4*)(a)     = *(const float4*)&As[k][ty * 4];
            *(float4*)(a + 4) = *(const float4*)&As[k][ty * 4 + 64];
            *(float4*)(b)     = *(const float4*)&Bs[k][tx * 4];
            *(float4*)(b + 4) = *(const float4*)&Bs[k][tx * 4 + 64];
#pragma unroll
            for (int i = 0; i < 8; i++)
#pragma unroll
                for (int j = 0; j < 8; j++) acc[i][j] = fmaf(a[i], b[j], acc[i][j]);
        }
        __syncthreads();
    }

#pragma unroll
    for (int i = 0; i < 8; i++) {
        int m = m0 + ty * 4 + (i & 3) + ((i >> 2) << 6);
        const float* mrow = mask + (size_t)m * Ss;
        float* orow = qk_out + ((size_t)bh * Ss + m) * Ss;
#pragma unroll
        for (int jg = 0; jg < 2; jg++) {
            int n = n0 + tx * 4 + jg * 64;
            float4 mv = *(const float4*)(mrow + n);
            float4 ov;
            ov.x = acc[i][jg * 4 + 0] + mv.x;
            ov.y = acc[i][jg * 4 + 1] + mv.y;
            ov.z = acc[i][jg * 4 + 2] + mv.z;
            ov.w = acc[i][jg * 4 + 3] + mv.w;
            *(float4*)(orow + n) = ov;
        }
    }
}

// ---------------- online softmax + P@V (reads qk once) ----------------
// grid: 2048 blocks (BH=64 heads x 32 row-blocks of 64 rows), block 256
// thread layout: row r = t/4 (64 rows), lane-group g = t%4 -> 16 O columns each
__global__ __launch_bounds__(256) void softmax_pv_kernel(const float* __restrict__ qk)
{
    __shared__ float pt[64 * 68];   // 64 rows x 64 cols, pitch 68 (17 float4)
    __shared__ float vt[64 * 64];   // 64 kv-rows x 64 cols
    const int blk = blockIdx.x;
    const int bh = blk >> 5;
    const int r0 = (blk & 31) << 6;
    const float* qrow = qk + ((size_t)bh * Ss + r0) * Ss;
    const float* vh = g_v + (size_t)bh * Ss * 64;
    const int t = threadIdx.x, r = t >> 2, g = t & 3;

    float o[16];
#pragma unroll
    for (int c = 0; c < 16; c++) o[c] = 0.f;
    float m_run = -1e30f, s_run = 0.f;

    for (int kc = 0; kc < Ss; kc += 64) {
#pragma unroll
        for (int i = 0; i < 4; i++) {
            int id = t + i * 256;            // 0..1023 float4 slots
            int row = id >> 4, c4 = id & 15;
            float4 pv = *(const float4*)(qrow + (size_t)row * Ss + kc + c4 * 4);
            ((float4*)pt)[row * 17 + c4] = pv;
            float4 vv = *(const float4*)(vh + (size_t)(kc + row) * 64 + c4 * 4);
            ((float4*)vt)[row * 16 + c4] = vv;
        }
        __syncthreads();

        const int base = r * 68 + g * 16;
        float lm = -1e30f;
#pragma unroll
        for (int j = 0; j < 16; j++) lm = fmaxf(lm, pt[base + j]);
        lm = fmaxf(lm, __shfl_xor_sync(0xffffffffu, lm, 1));
        lm = fmaxf(lm, __shfl_xor_sync(0xffffffffu, lm, 2));
        float mnew = fmaxf(m_run, lm);
        float alpha = __expf(m_run - mnew);
#pragma unroll
        for (int c = 0; c < 16; c++) o[c] *= alpha;
        float ls = 0.f;
#pragma unroll
        for (int j = 0; j < 16; j++) {
            float p = __expf(pt[base + j] - mnew);
            pt[base + j] = p;
            ls += p;
        }
        ls += __shfl_xor_sync(0xffffffffu, ls, 1);
        ls += __shfl_xor_sync(0xffffffffu, ls, 2);
        s_run = s_run * alpha + ls;
        m_run = mnew;
        __syncwarp();

        const int pb = r * 68;
#pragma unroll 4
        for (int j = 0; j < 64; j++) {
            float p = pt[pb + j];
            const float4* v4 = (const float4*)(vt + j * 64 + g * 16);
            float4 a0 = v4[0], a1 = v4[1], a2 = v4[2], a3 = v4[3];
            o[0]  = fmaf(p, a0.x, o[0]);  o[1]  = fmaf(p, a0.y, o[1]);
            o[2]  = fmaf(p, a0.z, o[2]);  o[3]  = fmaf(p, a0.w, o[3]);
            o[4]  = fmaf(p, a1.x, o[4]);  o[5]  = fmaf(p, a1.y, o[5]);
            o[6]  = fmaf(p, a1.z, o[6]);  o[7]  = fmaf(p, a1.w, o[7]);
            o[8]  = fmaf(p, a2.x, o[8]);  o[9]  = fmaf(p, a2.y, o[9]);
            o[10] = fmaf(p, a2.z, o[10]); o[11] = fmaf(p, a2.w, o[11]);
            o[12] = fmaf(p, a3.x, o[12]); o[13] = fmaf(p, a3.y, o[13]);
            o[14] = fmaf(p, a3.z, o[14]); o[15] = fmaf(p, a3.w, o[15]);
        }
        __syncthreads();
    }

    float inv = 1.0f / s_run;
    const int b = bh >> 4, h = bh & 15;
    // write pre-Wo activation into g_q (aliased scratch, Q is dead now)
    float* dst = g_q + (size_t)(b * Ss + r0 + r) * 1024 + h * 64 + g * 16;
#pragma unroll
    for (int q4 = 0; q4 < 4; q4++) {
        float4 w;
        w.x = o[q4 * 4 + 0] * inv; w.y = o[q4 * 4 + 1] * inv;
        w.z = o[q4 * 4 + 2] * inv; w.w = o[q4 * 4 + 3] * inv;
        *(float4*)(dst + q4 * 4) = w;
    }
}

// ---------------- output projection: out = attn @ Wo^T + bo ----------------
// grid: (8, 64), block 256; reads pre-Wo activations from g_q alias
__global__ __launch_bounds__(256) void oproj_kernel(const float* __restrict__ Wo,
                                                    const float* __restrict__ bo,
                                                    float* __restrict__ out)
{
    __shared__ float As[16][128];
    __shared__ float Bs[16][128];
    const int m0 = blockIdx.y * 128, n0 = blockIdx.x * 128;
    const int t = threadIdx.x;
    const int lr = t >> 2, lc = (t & 3) << 2;
    const int ty = t >> 4, tx = t & 15;

    float acc[8][8];
#pragma unroll
    for (int i = 0; i < 8; i++)
#pragma unroll
        for (int j = 0; j < 8; j++) acc[i][j] = 0.f;

    for (int kk = 0; kk < 1024; kk += 16) {
#pragma unroll
        for (int hf = 0; hf < 2; hf++) {
            int r = lr + hf * 64;
            float4 va = *(const float4*)(g_q + (size_t)(m0 + r) * 1024 + kk + lc);
            As[lc + 0][r] = va.x; As[lc + 1][r] = va.y;
            As[lc + 2][r] = va.z; As[lc + 3][r] = va.w;
            float4 vb = *(const float4*)(Wo + (size_t)(n0 + r) * 1024 + kk + lc);
            Bs[lc + 0][r] = vb.x; Bs[lc + 1][r] = vb.y;
            Bs[lc + 2][r] = vb.z; Bs[lc + 3][r] = vb.w;
        }
        __syncthreads();
#pragma unroll
        for (int k = 0; k < 16; k++) {
            float a[8], b[8];
            *(float4*)(a)     = *(const float4*)&As[k][ty * 4];
            *(float4*)(a + 4) = *(const float4*)&As[k][ty * 4 + 64];
            *(float4*)(b)     = *(const float4*)&Bs[k][tx * 4];
            *(float4*)(b + 4) = *(const float4*)&Bs[k][tx * 4 + 64];
#pragma unroll
            for (int i = 0; i < 8; i++)
#pragma unroll
                for (int j = 0; j < 8; j++) acc[i][j] = fmaf(a[i], b[j], acc[i][j]);
        }
        __syncthreads();
    }

#pragma unroll
    for (int i = 0; i < 8; i++) {
        int m = m0 + ty * 4 + (i & 3) + ((i >> 2) << 6);
        float* orow = out + (size_t)m * 1024;
#pragma unroll
        for (int jg = 0; jg < 2; jg++) {
            int n = n0 + tx * 4 + jg * 64;
            float4 bv = *(const float4*)(bo + n);
            float4 ov;
            ov.x = acc[i][jg * 4 + 0] + bv.x;
            ov.y = acc[i][jg * 4 + 1] + bv.y;
            ov.z = acc[i][jg * 4 + 2] + bv.z;
            ov.w = acc[i][jg * 4 + 3] + bv.w;
            *(float4*)(orow + n) = ov;
        }
    }
}

// ---------------- launch ----------------
extern "C" void kernel_launch(void* const* d_in, const int* in_sizes, int n_in,
                              void* d_out, int out_size)
{
    const float* x        = (const float*)d_in[0];
    const float* Wq       = (const float*)d_in[1];
    const float* bq       = (const float*)d_in[2];
    const float* Wk       = (const float*)d_in[3];
    const float* Wv       = (const float*)d_in[4];
    const float* bv       = (const float*)d_in[5];
    const float* Wo       = (const float*)d_in[6];
    const float* bo       = (const float*)d_in[7];
    const float* inv_freq = (const float*)d_in[8];
    const float* rbias    = (const float*)d_in[9];
    const float* mask     = (const float*)d_in[10];

    float* out    = (float*)d_out;
    float* qk_out = out + (size_t)BSn * Dd;   // second output: (B,H,S,S)

    rope_table_kernel<<<(Ss * 32 + 255) / 256, 256>>>(inv_freq, rbias);

    dim3 gA(8, 64, 3);
    qkv_kernel<<<gA, 256>>>(x, Wq, bq, Wk, Wv, bv);

    dim3 gB(16, 16, BHn);
    qk_kernel<<<gB, 256>>>(mask, qk_out);

    softmax_pv_kernel<<<2048, 256>>>(qk_out);

    dim3 gD(8, 64);
    oproj_kernel<<<gD, 256>>>(Wo, bo, out);
}